// round 5
// baseline (speedup 1.0000x reference)
#include <cuda_runtime.h>

// out = u2 + trilinear(u1, grid + u2), [B=2,160,160,160,3] fp32.
// Persistent-z blocks: each block owns an (8 x 16) xy-column, marches z in 10
// chunks of 16, double-buffered cp.async tile loads overlap compute.

#define Dd 160
#define Hh 160
#define Ww 160
#define HW  (Hh * Ww)
#define DHW (Dd * HW)

#define TX 8
#define TY 16
#define TZ 16
#define XH 3
#define YH 3
#define ZH 4
#define SX (TX + 2 * XH)     // 14
#define SY (TY + 2 * YH)     // 22
#define SZ (TZ + 2 * ZH)     // 24
#define RS (SZ * 3)          // 72 floats per (x,y) row
#define BUF (SX * SY * RS)   // 22176 floats = 88,704 B per buffer
#define NROW (SX * SY)       // 308
#define NCHUNK (Ww / TZ)     // 10
#define TPB 1024

extern __shared__ float smem[];   // 2 * BUF floats = 177,408 B

__device__ __forceinline__ void cp16(float* smem_dst, const float* gsrc)
{
    unsigned saddr = (unsigned)__cvta_generic_to_shared(smem_dst);
    asm volatile("cp.async.cg.shared.global [%0], [%1], 16;\n"
                 :: "r"(saddr), "l"(gsrc));
}

__global__ __launch_bounds__(TPB, 1)
void compose_pipe_kernel(const float* __restrict__ w1,
                         const float* __restrict__ w2,
                         float* __restrict__ out)
{
    const int x0 = blockIdx.x * TX;
    const int y0 = blockIdx.y * TY;
    const int b  = blockIdx.z;

    const int t    = threadIdx.x;
    const int lane = t & 31;
    const int wrp  = t >> 5;

    // compute mapping: warp -> (xh 0..3, yq 0..7); lane -> (ysub, hz)
    const int xh   = wrp >> 3;
    const int yq   = wrp & 7;
    const int ysub = lane >> 4;
    const int hz   = lane & 15;
    const int y    = y0 + yq * 2 + ysub;
    const int xb   = x0 + xh * 2;

    const float* __restrict__ w1b = w1 + (size_t)b * (size_t)DHW * 3;

    // ---- chunk tile loader (cp.async, one commit group per call) ----
    auto load_chunk = [&](int cz, float* buf) {
        const int z0   = cz * TZ;
        const int zlo  = max(z0 - ZH, 0);
        const int zhi  = min(z0 + TZ + ZH, Ww);
        const int nvec = ((zhi - zlo) * 3) >> 2;       // 15 or 18 float4
        const int dsto = (zlo - (z0 - ZH)) * 3;        // 0 or 12 (16B-aligned)
        for (int r = wrp; r < NROW; r += TPB / 32) {
            const int hx = r / SY;
            const int hy = r - hx * SY;
            const int cx = x0 - XH + hx;
            const int cy = y0 - YH + hy;
            if ((unsigned)cx < (unsigned)Dd && (unsigned)cy < (unsigned)Hh &&
                lane < nvec) {
                cp16(buf + r * RS + dsto + lane * 4,
                     w1b + ((size_t)(cx * Hh + cy) * Ww + zlo) * 3 + lane * 4);
            }
        }
        asm volatile("cp.async.commit_group;\n" ::: "memory");
    };

    // ---- prologue: start chunk 0 ----
    load_chunk(0, smem);

    for (int cz = 0; cz < NCHUNK; ++cz) {
        const int z0 = cz * TZ;
        const int z  = z0 + hz;
        float* buf   = smem + (cz & 1) * BUF;

        // prefetch u2 for this chunk (overlaps the cp.async wait)
        float pu[2][3];
        const int fb = (((b * Dd + xb) * Hh + y) * Ww + z) * 3;
#pragma unroll
        for (int j = 0; j < 2; ++j) {
            pu[j][0] = __ldg(w2 + fb + j * HW * 3 + 0);
            pu[j][1] = __ldg(w2 + fb + j * HW * 3 + 1);
            pu[j][2] = __ldg(w2 + fb + j * HW * 3 + 2);
        }

        // kick off next chunk into the other buffer (safe: its last readers
        // passed the trailing barrier of iteration cz-1)
        if (cz + 1 < NCHUNK) {
            load_chunk(cz + 1, smem + ((cz + 1) & 1) * BUF);
            asm volatile("cp.async.wait_group 1;\n" ::: "memory");
        } else {
            asm volatile("cp.async.wait_group 0;\n" ::: "memory");
        }
        __syncthreads();

#pragma unroll
        for (int j = 0; j < 2; ++j) {
            const int x = xb + j;
            const int f = fb + j * (HW * 3);
            const float u2x = pu[j][0], u2y = pu[j][1], u2z = pu[j][2];

            float lx = fminf(fmaxf((float)x + u2x, 0.0f), (float)(Dd - 1));
            float ly = fminf(fmaxf((float)y + u2y, 0.0f), (float)(Hh - 1));
            float lz = fminf(fmaxf((float)z + u2z, 0.0f), (float)(Ww - 1));

            const float fx = floorf(lx), fy = floorf(ly), fz = floorf(lz);
            const int ix0 = (int)fx, iy0 = (int)fy, iz0 = (int)fz;
            const float wx = lx - fx, wy = ly - fy, wz = lz - fz;
            const float wx0 = 1.0f - wx, wy0 = 1.0f - wy, wz0 = 1.0f - wz;

            const int ix1 = min(ix0 + 1, Dd - 1);
            const int iy1 = min(iy0 + 1, Hh - 1);
            const int iz1 = min(iz0 + 1, Ww - 1);

            const int sx0 = ix0 - (x0 - XH);
            const int sy0 = iy0 - (y0 - YH);
            const int sz0 = iz0 - (z0 - ZH);

            float ox, oy, oz;

            const bool fast = ((unsigned)sx0 <= (unsigned)(SX - 2)) &&
                              ((unsigned)sy0 <= (unsigned)(SY - 2)) &&
                              ((unsigned)sz0 <= (unsigned)(SZ - 2));
            if (fast) {
                const int sx1 = ix1 - (x0 - XH);
                const int sy1 = iy1 - (y0 - YH);
                const int za  = sz0 * 3;
                const int zb  = (iz1 - (z0 - ZH)) * 3;

                const float* p00 = buf + (sx0 * SY + sy0) * RS;
                const float* p01 = buf + (sx0 * SY + sy1) * RS;
                const float* p10 = buf + (sx1 * SY + sy0) * RS;
                const float* p11 = buf + (sx1 * SY + sy1) * RS;

                float acc[3];
#pragma unroll
                for (int c = 0; c < 3; ++c) {
                    const float v00 = p00[za + c] * wz0 + p00[zb + c] * wz;
                    const float v01 = p01[za + c] * wz0 + p01[zb + c] * wz;
                    const float v10 = p10[za + c] * wz0 + p10[zb + c] * wz;
                    const float v11 = p11[za + c] * wz0 + p11[zb + c] * wz;
                    acc[c] = (v00 * wy0 + v01 * wy) * wx0 +
                             (v10 * wy0 + v11 * wy) * wx;
                }
                ox = acc[0]; oy = acc[1]; oz = acc[2];
            } else {
                // Rare slow path (~0.1% threads): direct global gather.
                float a0 = 0.f, a1 = 0.f, a2 = 0.f;
#pragma unroll
                for (int cx = 0; cx < 2; ++cx) {
                    const int   ix  = cx ? ix1 : ix0;
                    const float wxx = cx ? wx : wx0;
#pragma unroll
                    for (int cy = 0; cy < 2; ++cy) {
                        const int   iy  = cy ? iy1 : iy0;
                        const float wxy = wxx * (cy ? wy : wy0);
#pragma unroll
                        for (int czn = 0; czn < 2; ++czn) {
                            const int   iz  = czn ? iz1 : iz0;
                            const float wgt = wxy * (czn ? wz : wz0);
                            const int off = ((ix * Hh + iy) * Ww + iz) * 3;
                            a0 = fmaf(__ldg(w1b + off + 0), wgt, a0);
                            a1 = fmaf(__ldg(w1b + off + 1), wgt, a1);
                            a2 = fmaf(__ldg(w1b + off + 2), wgt, a2);
                        }
                    }
                }
                ox = a0; oy = a1; oz = a2;
            }

            out[f + 0] = u2x + ox;
            out[f + 1] = u2y + oy;
            out[f + 2] = u2z + oz;
        }

        __syncthreads();   // all reads of buf done before it is refilled
    }
}

extern "C" void kernel_launch(void* const* d_in, const int* in_sizes, int n_in,
                              void* d_out, int out_size)
{
    const float* warp1 = (const float*)d_in[0];
    const float* warp2 = (const float*)d_in[1];
    float* out = (float*)d_out;

    static const size_t smem_bytes = 2 * BUF * sizeof(float);  // 177,408
    cudaFuncSetAttribute(compose_pipe_kernel,
                         cudaFuncAttributeMaxDynamicSharedMemorySize,
                         (int)smem_bytes);

    dim3 grid(Dd / TX, Hh / TY, 2);   // (20, 10, 2) = 400 blocks
    compose_pipe_kernel<<<grid, TPB, smem_bytes>>>(warp1, warp2, out);
}

// round 6
// speedup vs baseline: 1.1120x; 1.1120x over previous
#include <cuda_runtime.h>

// out = u2 + trilinear(u1, grid + u2), [B=2,160,160,160,3] fp32.
// One-shot smem tile per block (cp.async), sized so TWO blocks co-reside per
// SM: one block's tile fill overlaps the other's compute.

#define Dd 160
#define Hh 160
#define Ww 160
#define HW  (Hh * Ww)
#define DHW (Dd * HW)

#define TX 10
#define TY 10
#define TZ 16
#define HALO 4
#define SX (TX + 2 * HALO)   // 18
#define SY (TY + 2 * HALO)   // 18
#define SZ (TZ + 2 * HALO)   // 24
#define RS (SZ * 3)          // 72 floats per (x,y) row
#define NROW (SX * SY)       // 324
#define BUF (NROW * RS)      // 23328 floats = 93,312 B
#define TPB 512
#define NWARP (TPB / 32)     // 16
#define NTASK (TX * (TY / 2))// 50 warp tasks: (x, y-pair)

extern __shared__ float s[];

__device__ __forceinline__ void cp16(float* smem_dst, const float* gsrc)
{
    unsigned saddr = (unsigned)__cvta_generic_to_shared(smem_dst);
    asm volatile("cp.async.cg.shared.global [%0], [%1], 16;\n"
                 :: "r"(saddr), "l"(gsrc));
}

__global__ __launch_bounds__(TPB, 2)
void compose_tile2_kernel(const float* __restrict__ w1,
                          const float* __restrict__ w2,
                          float* __restrict__ out)
{
    // blockIdx.x = xy tile (x-major inner), blockIdx.y = z chunk, .z = batch.
    const int xt = blockIdx.x & 15;          // 0..15  (160/TX=16)
    const int yt = blockIdx.x >> 4;          // 0..15  (160/TY=16)
    const int x0 = xt * TX;
    const int y0 = yt * TY;
    const int z0 = blockIdx.y * TZ;
    const int b  = blockIdx.z;

    const int t    = threadIdx.x;
    const int lane = t & 31;
    const int wrp  = t >> 5;

    const float* __restrict__ w1b = w1 + (size_t)b * (size_t)DHW * 3;

    // ---- One-shot tile fill via cp.async, flat (row, vec) indexing ----
    if (z0 >= HALO && z0 + TZ + HALO <= Ww) {
        // interior in z: nvec = 18, dsto = 0, zlo = z0-4  (compile-time divs)
        const size_t zoff = (size_t)(z0 - HALO) * 3;
        for (int idx = t; idx < NROW * 18; idx += TPB) {
            const int row = idx / 18;
            const int v   = idx - row * 18;
            const int hx  = row / SY;
            const int hy  = row - hx * SY;
            const int cx  = x0 - HALO + hx;
            const int cy  = y0 - HALO + hy;
            if ((unsigned)cx < (unsigned)Dd && (unsigned)cy < (unsigned)Hh)
                cp16(s + row * RS + v * 4,
                     w1b + (size_t)(cx * Hh + cy) * (Ww * 3) + zoff + v * 4);
        }
    } else {
        // z edge: range 20 slots -> nvec = 15
        const int zlo  = (z0 == 0) ? 0 : z0 - HALO;
        const int dsto = (z0 == 0) ? 12 : 0;
        const size_t zoff = (size_t)zlo * 3;
        for (int idx = t; idx < NROW * 15; idx += TPB) {
            const int row = idx / 15;
            const int v   = idx - row * 15;
            const int hx  = row / SY;
            const int hy  = row - hx * SY;
            const int cx  = x0 - HALO + hx;
            const int cy  = y0 - HALO + hy;
            if ((unsigned)cx < (unsigned)Dd && (unsigned)cy < (unsigned)Hh)
                cp16(s + row * RS + dsto + v * 4,
                     w1b + (size_t)(cx * Hh + cy) * (Ww * 3) + zoff + v * 4);
        }
    }
    asm volatile("cp.async.commit_group;\n" ::: "memory");

    // ---- Compute mapping: lane = (ysub, z16); warp task = (x, y-pair) ----
    const int ysub = lane >> 4;          // 0..1
    const int hz   = lane & 15;          // 0..15
    const int z    = z0 + hz;

    // Prefetch u2 for the warp's first task while the tile streams in.
    int task = wrp;
    int nf;
    float nux, nuy, nuz;
    {
        const int xi = task / 5, yp = task - xi * 5;
        const int x_ = x0 + xi, y_ = y0 + yp * 2 + ysub;
        nf  = (((b * Dd + x_) * Hh + y_) * Ww + z) * 3;
        nux = __ldg(w2 + nf + 0);
        nuy = __ldg(w2 + nf + 1);
        nuz = __ldg(w2 + nf + 2);
    }

    asm volatile("cp.async.wait_group 0;\n" ::: "memory");
    __syncthreads();

    for (; task < NTASK; task += NWARP) {
        const int xi = task / 5;
        const int x  = x0 + xi;
        const int y  = y0 + (task - xi * 5) * 2 + ysub;
        const int f  = nf;
        const float u2x = nux, u2y = nuy, u2z = nuz;

        if (task + NWARP < NTASK) {      // prefetch next task's u2
            const int xi2 = (task + NWARP) / 5;
            const int yp2 = (task + NWARP) - xi2 * 5;
            nf  = (((b * Dd + x0 + xi2) * Hh + y0 + yp2 * 2 + ysub) * Ww + z) * 3;
            nux = __ldg(w2 + nf + 0);
            nuy = __ldg(w2 + nf + 1);
            nuz = __ldg(w2 + nf + 2);
        }

        float lx = fminf(fmaxf((float)x + u2x, 0.0f), (float)(Dd - 1));
        float ly = fminf(fmaxf((float)y + u2y, 0.0f), (float)(Hh - 1));
        float lz = fminf(fmaxf((float)z + u2z, 0.0f), (float)(Ww - 1));

        const float fx = floorf(lx), fy = floorf(ly), fz = floorf(lz);
        const int ix0 = (int)fx, iy0 = (int)fy, iz0 = (int)fz;
        const float wx = lx - fx, wy = ly - fy, wz = lz - fz;
        const float wx0 = 1.0f - wx, wy0 = 1.0f - wy, wz0 = 1.0f - wz;

        const int ix1 = min(ix0 + 1, Dd - 1);
        const int iy1 = min(iy0 + 1, Hh - 1);
        const int iz1 = min(iz0 + 1, Ww - 1);

        const int sx0 = ix0 - (x0 - HALO);
        const int sy0 = iy0 - (y0 - HALO);
        const int sz0 = iz0 - (z0 - HALO);

        float ox, oy, oz;

        const bool fast = ((unsigned)sx0 <= (unsigned)(SX - 2)) &&
                          ((unsigned)sy0 <= (unsigned)(SY - 2)) &&
                          ((unsigned)sz0 <= (unsigned)(SZ - 2));
        if (fast) {
            const int sx1 = ix1 - (x0 - HALO);
            const int sy1 = iy1 - (y0 - HALO);
            const int za  = sz0 * 3;
            const int zb  = (iz1 - (z0 - HALO)) * 3;

            const float* p00 = s + (sx0 * SY + sy0) * RS;
            const float* p01 = s + (sx0 * SY + sy1) * RS;
            const float* p10 = s + (sx1 * SY + sy0) * RS;
            const float* p11 = s + (sx1 * SY + sy1) * RS;

            float acc[3];
#pragma unroll
            for (int c = 0; c < 3; ++c) {
                const float v00 = p00[za + c] * wz0 + p00[zb + c] * wz;
                const float v01 = p01[za + c] * wz0 + p01[zb + c] * wz;
                const float v10 = p10[za + c] * wz0 + p10[zb + c] * wz;
                const float v11 = p11[za + c] * wz0 + p11[zb + c] * wz;
                acc[c] = (v00 * wy0 + v01 * wy) * wx0 +
                         (v10 * wy0 + v11 * wy) * wx;
            }
            ox = acc[0]; oy = acc[1]; oz = acc[2];
        } else {
            // Rare slow path (~0.02% of threads): direct global gather.
            float a0 = 0.f, a1 = 0.f, a2 = 0.f;
#pragma unroll
            for (int cx = 0; cx < 2; ++cx) {
                const int   ix  = cx ? ix1 : ix0;
                const float wxx = cx ? wx : wx0;
#pragma unroll
                for (int cy = 0; cy < 2; ++cy) {
                    const int   iy  = cy ? iy1 : iy0;
                    const float wxy = wxx * (cy ? wy : wy0);
#pragma unroll
                    for (int cz = 0; cz < 2; ++cz) {
                        const int   iz  = cz ? iz1 : iz0;
                        const float wgt = wxy * (cz ? wz : wz0);
                        const int off = ((ix * Hh + iy) * Ww + iz) * 3;
                        a0 = fmaf(__ldg(w1b + off + 0), wgt, a0);
                        a1 = fmaf(__ldg(w1b + off + 1), wgt, a1);
                        a2 = fmaf(__ldg(w1b + off + 2), wgt, a2);
                    }
                }
            }
            ox = a0; oy = a1; oz = a2;
        }

        out[f + 0] = u2x + ox;
        out[f + 1] = u2y + oy;
        out[f + 2] = u2z + oz;
    }
}

extern "C" void kernel_launch(void* const* d_in, const int* in_sizes, int n_in,
                              void* d_out, int out_size)
{
    const float* warp1 = (const float*)d_in[0];
    const float* warp2 = (const float*)d_in[1];
    float* out = (float*)d_out;

    static const size_t smem_bytes = BUF * sizeof(float);  // 93,312
    cudaFuncSetAttribute(compose_tile2_kernel,
                         cudaFuncAttributeMaxDynamicSharedMemorySize,
                         (int)smem_bytes);

    // 256 xy tiles (x-major), 10 z chunks, 2 batches = 5120 blocks.
    dim3 grid(256, Ww / TZ, 2);
    compose_tile2_kernel<<<grid, TPB, smem_bytes>>>(warp1, warp2, out);
}